// round 11
// baseline (speedup 1.0000x reference)
#include <cuda_runtime.h>
#include <cstdint>

// Problem constants
#define BB  8
#define TT  48000
#define HH  60
#define CC  100
#define NFF 5

// ---------------------------------------------------------------------------
// Scratch per batch:
//   [0, 48000)      elems -> (in place) final inclusive scan s[t]
//   [48000, 51000)  B1   : 3000 block sums of 16 elems
//   [51008, 54008)  ISB1 : inclusive scan of B1
//   [54016, 54204)  B2   : 188 block sums of 16 B1s (last block has 8)
//   [54208, 54396)  ISB2 : inclusive scan of B2
//   [54400, 54412)  B3   : 12 block sums of 16 B2s (last block has 12)
//   [54416, 54428)  S3   : inclusive scan of B3 (sequential)
// ---------------------------------------------------------------------------
__device__ float g_scan[BB][56320];

#define OFF_B1   48000
#define OFF_ISB1 51008
#define OFF_B2   54016
#define OFF_ISB2 54208
#define OFF_B3   54400
#define OFF_S3   54416

// ---------------------------------------------------------------------------
// Accurate sin for x >= 0, x < ~3.2e5. ~2e-7 abs error, branch-free.
// ---------------------------------------------------------------------------
__device__ __forceinline__ float accurate_sin_pos(float x) {
    float t  = x * 0.636619772367581343f;           // 2/pi
    int   q  = __float2int_rn(t);
    float qf = __int2float_rn(q);
    float r  = fmaf(qf, -1.57079637050628662109375f, x);  // -fl(pi/2)
    r        = fmaf(qf,  4.37113900018370e-8f, r);        // fl(pi/2)-pi/2 tail
    float z  = r * r;
    float ss = fmaf(-1.9515295891e-4f, z, 8.3321608736e-3f);
    ss       = fmaf(ss, z, -1.6666654611e-1f);
    float ps = fmaf(r, z * ss, r);
    float cc = fmaf(2.443315711809948e-5f, z, -1.388731625493765e-3f);
    cc       = fmaf(cc, z, 4.166664568298827e-2f);
    float pc = fmaf(cc, z * z, fmaf(-0.5f, z, 1.0f));
    float res = (q & 1) ? pc : ps;
    return (q & 2) ? -res : res;
}

// ---------------------------------------------------------------------------
// Kernel 1: XLA ReduceWindowRewriter (base 16) blocked cumsum, sequential
// inner scans (the best-fit structure, from round 3), with elems computed as
//   elems = fl32( fl32(6.2831855f * f0) * fl32(1/24000) )
// (divide-by-constant lowered to multiply-by-reciprocal; fl(1/24000) carries
// a -2.86e-8 coherent rel bias that matches the observed residual).
// ---------------------------------------------------------------------------
__global__ void phase_scan_kernel(const float* __restrict__ f0,
                                  const float* __restrict__ init_phase,
                                  float* __restrict__ out, int out_size) {
    const int b  = blockIdx.x;
    const int bd = blockDim.x;
    float* g = g_scan[b];
    const float* fb = f0 + (size_t)b * TT;

    const float C1   = 6.2831854820251465f;     // fl(2*pi)
    const float RINV = 1.0f / 24000.0f;         // fl(1/24000), rel err -2.86e-8
    for (int t = threadIdx.x; t < TT; t += bd) {
        float num = C1 * fb[t];
        g[t] = num * RINV;
    }
    __syncthreads();

    // B1[r] = sequential sum of elems[16r .. 16r+15], r in [0,3000)
    for (int r = threadIdx.x; r < 3000; r += bd) {
        float acc = 0.0f;
        const float* e = g + 16 * r;
#pragma unroll
        for (int j = 0; j < 16; j++) acc += e[j];
        g[OFF_B1 + r] = acc;
    }
    __syncthreads();

    // B2[q] = sequential sum of B1[16q ..], q in [0,188); last block 8 real
    for (int q = threadIdx.x; q < 188; q += bd) {
        float acc = 0.0f;
        const int nj = min(16, 3000 - 16 * q);
        const float* e = g + OFF_B1 + 16 * q;
        for (int j = 0; j < nj; j++) acc += e[j];
        g[OFF_B2 + q] = acc;
    }
    __syncthreads();

    // B3[k] = sequential sum of B2[16k ..], k in [0,12); last block 12 real
    for (int k = threadIdx.x; k < 12; k += bd) {
        float acc = 0.0f;
        const int nj = min(16, 188 - 16 * k);
        const float* e = g + OFF_B2 + 16 * k;
        for (int j = 0; j < nj; j++) acc += e[j];
        g[OFF_B3 + k] = acc;
    }
    __syncthreads();

    // S3 = naive inclusive sequential scan of B3 (12 <= 16)
    if (threadIdx.x == 0) {
        float acc = 0.0f;
        for (int k = 0; k < 12; k++) {
            acc += g[OFF_B3 + k];
            g[OFF_S3 + k] = acc;
        }
    }
    __syncthreads();

    // ISB2[q] = fl( S3[x-1] + seqprefix(B2[16x .. q]) ), carry 0 for x==0
    for (int q = threadIdx.x; q < 188; q += bd) {
        const int x = q >> 4, y = q & 15;
        float acc = 0.0f;
        const float* e = g + OFF_B2 + 16 * x;
        for (int j = 0; j <= y; j++) acc += e[j];
        float carry = (x > 0) ? g[OFF_S3 + x - 1] : 0.0f;
        g[OFF_ISB2 + q] = (x > 0) ? (carry + acc) : acc;
    }
    __syncthreads();

    // ISB1[m] = fl( ISB2[x-1] + seqprefix(B1[16x .. m]) )
    for (int m = threadIdx.x; m < 3000; m += bd) {
        const int x = m >> 4, y = m & 15;
        float acc = 0.0f;
        const float* e = g + OFF_B1 + 16 * x;
        for (int j = 0; j <= y; j++) acc += e[j];
        float carry = (x > 0) ? g[OFF_ISB2 + x - 1] : 0.0f;
        g[OFF_ISB1 + m] = (x > 0) ? (carry + acc) : acc;
    }
    __syncthreads();

    // s[16r+j] = fl( ISB1[r-1] + seqprefix(elems[16r .. 16r+j]) ), in place
    for (int r = threadIdx.x; r < 3000; r += bd) {
        float carry = (r > 0) ? g[OFF_ISB1 + r - 1] : 0.0f;
        float acc = 0.0f;
        float* e = g + 16 * r;
#pragma unroll
        for (int j = 0; j < 16; j++) {
            acc += e[j];            // read elem before overwrite (same thread)
            e[j] = (r > 0) ? (carry + acc) : acc;
        }
    }
    __syncthreads();

    if (threadIdx.x == 0 && out_size >= BB * TT + BB) {
        const float TWO_PI = 6.2831854820251465f;
        float ph = g[TT - 1] + init_phase[b];
        out[BB * TT + b] = fmodf(ph, TWO_PI);
    }
}

// ---------------------------------------------------------------------------
// Kernel 2: main oscillator. One thread per (b, t); loops h = 1..60.
// ---------------------------------------------------------------------------
__global__ void __launch_bounds__(256)
osc_kernel(const float* __restrict__ f0g,
           const float* __restrict__ amps,
           const float* __restrict__ ffq,
           const float* __restrict__ fbw,
           const float* __restrict__ fam,
           const float* __restrict__ init_phase,
           float* __restrict__ out) {
    const int idx = blockIdx.x * blockDim.x + threadIdx.x;
    if (idx >= BB * TT) return;
    const int b = idx / TT;
    const int t = idx - b * TT;

    const float f0    = f0g[idx];
    const float phase = g_scan[b][t] + init_phase[b];

    // Linear interp of formant params (align_corners=True), fp32 like ref.
    const float K = (float)(99.0 / 47999.0);
    float src = (float)t * K;
    int i0 = (int)floorf(src);
    i0 = min(max(i0, 0), CC - 2);
    const float frac = src - (float)i0;
    const float w0 = 1.0f - frac;

    const int base0 = (b * CC + i0) * NFF;
    const int base1 = base0 + NFF;

    float freq[NFF], bwsq[NFF], num[NFF];
#pragma unroll
    for (int f = 0; f < NFF; f++) {
        float fr = ffq[base0 + f] * w0 + ffq[base1 + f] * frac;
        float bw = fbw[base0 + f] * w0 + fbw[base1 + f] * frac;
        float am = fam[base0 + f] * w0 + fam[base1 + f] * frac;
        freq[f] = fr;
        bwsq[f] = bw * bw;
        num[f]  = (am * bw) * bw;
    }

    const float4* av = reinterpret_cast<const float4*>(amps + (size_t)idx * HH);

    float acc = 0.0f;
    float hfv = 1.0f;
#pragma unroll 1
    for (int j = 0; j < HH / 4; j++) {
        float4 a4 = av[j];
        float aarr[4] = {a4.x, a4.y, a4.z, a4.w};
#pragma unroll
        for (int u = 0; u < 4; u++) {
            const float hfreq = f0 * hfv;
            const float x     = phase * hfv;
            const float osc   = accurate_sin_pos(x);
            float fac = 1.0f;
#pragma unroll
            for (int f = 0; f < NFF; f++) {
                float d   = hfreq - freq[f];
                float den = fmaf(d, d, bwsq[f]);
                fac *= 1.0f + __fdividef(num[f], den);
            }
            float a = (hfreq < 12000.0f) ? aarr[u] : 0.0f;
            acc = fmaf(osc * fac, a, acc);
            hfv += 1.0f;
        }
    }

    out[idx] = (f0 > 0.0f) ? acc : 0.0f;
}

// ---------------------------------------------------------------------------
extern "C" void kernel_launch(void* const* d_in, const int* in_sizes, int n_in,
                              void* d_out, int out_size) {
    const float* f0   = (const float*)d_in[0];
    const float* amps = (const float*)d_in[1];
    const float* ffq  = (const float*)d_in[2];
    const float* fbw  = (const float*)d_in[3];
    const float* fam  = (const float*)d_in[4];
    const float* ip   = (const float*)d_in[5];
    float* out = (float*)d_out;

    phase_scan_kernel<<<BB, 1024>>>(f0, ip, out, out_size);

    const int total = BB * TT;
    osc_kernel<<<(total + 255) / 256, 256>>>(f0, amps, ffq, fbw, fam, ip, out);
}

// round 12
// speedup vs baseline: 1.1013x; 1.1013x over previous
#include <cuda_runtime.h>
#include <cstdint>

// Problem constants
#define BB  8
#define TT  48000
#define HH  60
#define CC  100
#define NFF 5

// Final phase per (b,t) — produced by scan kernel, consumed by osc kernel.
__device__ float g_scan[BB][TT];

// Shared-memory scratch layout (floats) for the scan kernel:
//   [0,      48000) SE  : elems -> (in place) final inclusive scan
//   [48000,  51000) SB1 : 3000 B1 block sums -> (in place) ISB1
//   [51000,  51188) B2  : 188 B2 block sums  -> (in place) ISB2
//   [51188,  51200) B3  : 12 B3 block sums   -> (in place) S3
#define SM_SE   0
#define SM_SB1  48000
#define SM_B2   51000
#define SM_B3   51188
#define SM_FLOATS 51200
#define SM_BYTES (SM_FLOATS * 4)

// ---------------------------------------------------------------------------
// Accurate sin for x >= 0, x < ~3.2e5. ~2e-7 abs error, branch-free.
// ---------------------------------------------------------------------------
__device__ __forceinline__ float accurate_sin_pos(float x) {
    float t  = x * 0.636619772367581343f;           // 2/pi
    int   q  = __float2int_rn(t);
    float qf = __int2float_rn(q);
    float r  = fmaf(qf, -1.57079637050628662109375f, x);  // -fl(pi/2)
    r        = fmaf(qf,  4.37113900018370e-8f, r);        // fl(pi/2)-pi/2 tail
    float z  = r * r;
    float ss = fmaf(-1.9515295891e-4f, z, 8.3321608736e-3f);
    ss       = fmaf(ss, z, -1.6666654611e-1f);
    float ps = fmaf(r, z * ss, r);
    float cc = fmaf(2.443315711809948e-5f, z, -1.388731625493765e-3f);
    cc       = fmaf(cc, z, 4.166664568298827e-2f);
    float pc = fmaf(cc, z * z, fmaf(-0.5f, z, 1.0f));
    float res = (q & 1) ? pc : ps;
    return (q & 2) ? -res : res;
}

__device__ __forceinline__ float rcp_approx(float x) {
    float r;
    asm("rcp.approx.f32 %0, %1;" : "=f"(r) : "f"(x));
    return r;
}

// ---------------------------------------------------------------------------
// Kernel 1: XLA ReduceWindowRewriter (base 16) blocked cumsum, sequential
// inner scans, elems = fl32( fl32(6.2831855f * f0) * fl32(1/24000) ).
// Bit-identical arithmetic to the round-11 passing version; all intermediate
// levels live in shared memory (204.8 KB) instead of global scratch.
// ---------------------------------------------------------------------------
__global__ void __launch_bounds__(1024)
phase_scan_kernel(const float* __restrict__ f0,
                  const float* __restrict__ init_phase,
                  float* __restrict__ out, int out_size) {
    extern __shared__ float sm[];
    const int b  = blockIdx.x;
    const int bd = blockDim.x;
    const float* fb = f0 + (size_t)b * TT;
    float* gout = g_scan[b];

    const float C1   = 6.2831854820251465f;     // fl(2*pi)
    const float RINV = 1.0f / 24000.0f;         // fl(1/24000)

    // Phase 0: elems
    for (int t = threadIdx.x; t < TT; t += bd) {
        float num = C1 * fb[t];
        sm[SM_SE + t] = num * RINV;
    }
    __syncthreads();

    // Phase 1: B1[r] = seq sum of elems[16r..16r+15]
    for (int r = threadIdx.x; r < 3000; r += bd) {
        float acc = 0.0f;
        const float* e = sm + SM_SE + 16 * r;
#pragma unroll
        for (int j = 0; j < 16; j++) acc += e[j];
        sm[SM_SB1 + r] = acc;
    }
    __syncthreads();

    // Phase 2: B2[q] = seq sum of B1[16q..]; last block 8 real
    for (int q = threadIdx.x; q < 188; q += bd) {
        float acc = 0.0f;
        const int nj = min(16, 3000 - 16 * q);
        const float* e = sm + SM_SB1 + 16 * q;
        for (int j = 0; j < nj; j++) acc += e[j];
        sm[SM_B2 + q] = acc;
    }
    __syncthreads();

    // Phase 3: B3[k] = seq sum of B2[16k..]; last block 12 real
    for (int k = threadIdx.x; k < 12; k += bd) {
        float acc = 0.0f;
        const int nj = min(16, 188 - 16 * k);
        const float* e = sm + SM_B2 + 16 * k;
        for (int j = 0; j < nj; j++) acc += e[j];
        sm[SM_B3 + k] = acc;
    }
    __syncthreads();

    // Phase 4: S3 = in-place inclusive sequential scan of B3
    if (threadIdx.x == 0) {
        float acc = 0.0f;
        for (int k = 0; k < 12; k++) {
            acc += sm[SM_B3 + k];
            sm[SM_B3 + k] = acc;
        }
    }
    __syncthreads();

    // Phase 5: ISB2 in place over B2: per 16-block k, carry = S3[k-1]
    for (int k = threadIdx.x; k < 12; k += bd) {
        const float carry = (k > 0) ? sm[SM_B3 + k - 1] : 0.0f;
        const int nj = min(16, 188 - 16 * k);
        float acc = 0.0f;
        float* e = sm + SM_B2 + 16 * k;
        for (int j = 0; j < nj; j++) {
            acc += e[j];
            e[j] = (k > 0) ? (carry + acc) : acc;
        }
    }
    __syncthreads();

    // Phase 6: ISB1 in place over B1: per 16-block x, carry = ISB2[x-1]
    for (int x = threadIdx.x; x < 188; x += bd) {
        const float carry = (x > 0) ? sm[SM_B2 + x - 1] : 0.0f;
        const int nj = min(16, 3000 - 16 * x);
        float acc = 0.0f;
        float* e = sm + SM_SB1 + 16 * x;
        for (int j = 0; j < nj; j++) {
            acc += e[j];
            e[j] = (x > 0) ? (carry + acc) : acc;
        }
    }
    __syncthreads();

    // Phase 7: final s[16r+j] = ISB1[r-1] + seqprefix(elems); write to global
    for (int r = threadIdx.x; r < 3000; r += bd) {
        const float carry = (r > 0) ? sm[SM_SB1 + r - 1] : 0.0f;
        float acc = 0.0f;
        const float* e = sm + SM_SE + 16 * r;
        float* o = gout + 16 * r;
#pragma unroll
        for (int j = 0; j < 16; j++) {
            acc += e[j];
            o[j] = (r > 0) ? (carry + acc) : acc;
        }
    }
    __syncthreads();

    if (threadIdx.x == 0 && out_size >= BB * TT + BB) {
        const float TWO_PI = 6.2831854820251465f;
        float last = gout[TT - 1];
        float ph = last + init_phase[b];
        out[BB * TT + b] = fmodf(ph, TWO_PI);
    }
}

// ---------------------------------------------------------------------------
// Kernel 2: main oscillator. One thread per (b, t); loops h = 1..60.
// ---------------------------------------------------------------------------
__global__ void __launch_bounds__(256)
osc_kernel(const float* __restrict__ f0g,
           const float* __restrict__ amps,
           const float* __restrict__ ffq,
           const float* __restrict__ fbw,
           const float* __restrict__ fam,
           const float* __restrict__ init_phase,
           float* __restrict__ out) {
    const int idx = blockIdx.x * blockDim.x + threadIdx.x;
    if (idx >= BB * TT) return;
    const int b = idx / TT;
    const int t = idx - b * TT;

    const float f0    = f0g[idx];
    const float phase = g_scan[b][t] + init_phase[b];

    // Linear interp of formant params (align_corners=True), fp32 like ref.
    const float K = (float)(99.0 / 47999.0);
    float src = (float)t * K;
    int i0 = (int)floorf(src);
    i0 = min(max(i0, 0), CC - 2);
    const float frac = src - (float)i0;
    const float w0 = 1.0f - frac;

    const int base0 = (b * CC + i0) * NFF;
    const int base1 = base0 + NFF;

    float freq[NFF], bwsq[NFF], num[NFF];
#pragma unroll
    for (int f = 0; f < NFF; f++) {
        float fr = ffq[base0 + f] * w0 + ffq[base1 + f] * frac;
        float bw = fbw[base0 + f] * w0 + fbw[base1 + f] * frac;
        float am = fam[base0 + f] * w0 + fam[base1 + f] * frac;
        freq[f] = fr;
        bwsq[f] = bw * bw;
        num[f]  = (am * bw) * bw;
    }

    const float4* av = reinterpret_cast<const float4*>(amps + (size_t)idx * HH);

    float acc = 0.0f;
    float hfv = 1.0f;
#pragma unroll 1
    for (int j = 0; j < HH / 4; j++) {
        float4 a4 = av[j];
        float aarr[4] = {a4.x, a4.y, a4.z, a4.w};
#pragma unroll
        for (int u = 0; u < 4; u++) {
            const float hfreq = f0 * hfv;
            const float x     = phase * hfv;
            const float osc   = accurate_sin_pos(x);
            float fac = 1.0f;
#pragma unroll
            for (int f = 0; f < NFF; f++) {
                float d   = hfreq - freq[f];
                float den = fmaf(d, d, bwsq[f]);
                fac *= fmaf(num[f], rcp_approx(den), 1.0f);
            }
            float a = (hfreq < 12000.0f) ? aarr[u] : 0.0f;
            acc = fmaf(osc * fac, a, acc);
            hfv += 1.0f;
        }
    }

    out[idx] = (f0 > 0.0f) ? acc : 0.0f;
}

// ---------------------------------------------------------------------------
extern "C" void kernel_launch(void* const* d_in, const int* in_sizes, int n_in,
                              void* d_out, int out_size) {
    const float* f0   = (const float*)d_in[0];
    const float* amps = (const float*)d_in[1];
    const float* ffq  = (const float*)d_in[2];
    const float* fbw  = (const float*)d_in[3];
    const float* fam  = (const float*)d_in[4];
    const float* ip   = (const float*)d_in[5];
    float* out = (float*)d_out;

    static bool attr_set = false;
    if (!attr_set) {
        cudaFuncSetAttribute(phase_scan_kernel,
                             cudaFuncAttributeMaxDynamicSharedMemorySize,
                             SM_BYTES);
        attr_set = true;
    }

    phase_scan_kernel<<<BB, 1024, SM_BYTES>>>(f0, ip, out, out_size);

    const int total = BB * TT;
    osc_kernel<<<(total + 255) / 256, 256>>>(f0, amps, ffq, fbw, fam, ip, out);
}

// round 15
// speedup vs baseline: 1.6931x; 1.5374x over previous
#include <cuda_runtime.h>
#include <cstdint>

// Problem constants
#define BB  8
#define TT  48000
#define HH  60
#define CC  100
#define NFF 5

// Global intermediates
__device__ float g_b1[BB][3000];     // level-1 block sums
__device__ float g_isb1[BB][3000];   // inclusive scan of B1 (composed)
__device__ float g_scan[BB][TT];     // final phase cumsum

// ---------------------------------------------------------------------------
// Accurate sin for x >= 0, x < ~3.2e5. ~2e-7 abs error, branch-free.
// ---------------------------------------------------------------------------
__device__ __forceinline__ float accurate_sin_pos(float x) {
    float t  = x * 0.636619772367581343f;           // 2/pi
    int   q  = __float2int_rn(t);
    float qf = __int2float_rn(q);
    float r  = fmaf(qf, -1.57079637050628662109375f, x);  // -fl(pi/2)
    r        = fmaf(qf,  4.37113900018370e-8f, r);        // fl(pi/2)-pi/2 tail
    float z  = r * r;
    float ss = fmaf(-1.9515295891e-4f, z, 8.3321608736e-3f);
    ss       = fmaf(ss, z, -1.6666654611e-1f);
    float ps = fmaf(r, z * ss, r);
    float cc = fmaf(2.443315711809948e-5f, z, -1.388731625493765e-3f);
    cc       = fmaf(cc, z, 4.166664568298827e-2f);
    float pc = fmaf(cc, z * z, fmaf(-0.5f, z, 1.0f));
    float res = (q & 1) ? pc : ps;
    return (q & 2) ? -res : res;
}

#define C1_2PI 6.2831854820251465f
#define RINV24 (1.0f / 24000.0f)

// elems = fl32( fl32(C1 * f0) * fl32(1/24000) ) — intrinsics forbid FMA
// contraction, reproducing the stored-and-reloaded rounding of rounds 11/12.
__device__ __forceinline__ float elem_of(float f0v) {
    return __fmul_rn(__fmul_rn(C1_2PI, f0v), RINV24);
}

// ---------------------------------------------------------------------------
// Kernel A: B1[b][r] = sequential sum of elems[16r..16r+15], chip-wide.
// ---------------------------------------------------------------------------
__global__ void __launch_bounds__(256)
scan_b1_kernel(const float* __restrict__ f0) {
    const int rg = blockIdx.x * blockDim.x + threadIdx.x;
    if (rg >= BB * 3000) return;
    const int b  = rg / 3000;
    const int rl = rg - b * 3000;

    const float4* src = reinterpret_cast<const float4*>(
        f0 + (size_t)b * TT + 16 * rl);
    float acc = 0.0f;
#pragma unroll
    for (int v = 0; v < 4; v++) {
        float4 x = src[v];
        acc = __fadd_rn(acc, elem_of(x.x));
        acc = __fadd_rn(acc, elem_of(x.y));
        acc = __fadd_rn(acc, elem_of(x.z));
        acc = __fadd_rn(acc, elem_of(x.w));
    }
    g_b1[b][rl] = acc;
}

// ---------------------------------------------------------------------------
// Kernel B: upper levels per batch: B2(188) -> B3(12) -> S3 -> ISB2 -> ISB1.
// One block per batch; sequential inner scans, carry composition as rw-16.
// ---------------------------------------------------------------------------
__global__ void __launch_bounds__(256)
scan_upper_kernel() {
    __shared__ float sb1[3000];
    __shared__ float sb2[188];
    __shared__ float sb3[12];

    const int b   = blockIdx.x;
    const int tid = threadIdx.x;
    const int bd  = blockDim.x;

    for (int i = tid; i < 3000; i += bd) sb1[i] = g_b1[b][i];
    __syncthreads();

    // B2[q] = seq sum of B1[16q..]; last block 8 real
    for (int q = tid; q < 188; q += bd) {
        float acc = 0.0f;
        const int nj = min(16, 3000 - 16 * q);
        const float* e = sb1 + 16 * q;
        for (int j = 0; j < nj; j++) acc = __fadd_rn(acc, e[j]);
        sb2[q] = acc;
    }
    __syncthreads();

    // B3[k] = seq sum of B2[16k..]; last block 12 real
    if (tid < 12) {
        float acc = 0.0f;
        const int nj = min(16, 188 - 16 * tid);
        const float* e = sb2 + 16 * tid;
        for (int j = 0; j < nj; j++) acc = __fadd_rn(acc, e[j]);
        sb3[tid] = acc;
    }
    __syncthreads();

    // S3 = in-place inclusive sequential scan of B3
    if (tid == 0) {
        float acc = 0.0f;
        for (int k = 0; k < 12; k++) {
            acc = __fadd_rn(acc, sb3[k]);
            sb3[k] = acc;
        }
    }
    __syncthreads();

    // ISB2 in place over B2: per 16-block k, carry = S3[k-1]
    if (tid < 12) {
        const float carry = (tid > 0) ? sb3[tid - 1] : 0.0f;
        const int nj = min(16, 188 - 16 * tid);
        float acc = 0.0f;
        float* e = sb2 + 16 * tid;
        for (int j = 0; j < nj; j++) {
            acc = __fadd_rn(acc, e[j]);
            e[j] = (tid > 0) ? __fadd_rn(carry, acc) : acc;
        }
    }
    __syncthreads();

    // ISB1: per 16-block x of B1, carry = ISB2[x-1]; write to global
    for (int x = tid; x < 188; x += bd) {
        const float carry = (x > 0) ? sb2[x - 1] : 0.0f;
        const int nj = min(16, 3000 - 16 * x);
        float acc = 0.0f;
        const float* e = sb1 + 16 * x;
        float* o = g_isb1[b] + 16 * x;
        for (int j = 0; j < nj; j++) {
            acc = __fadd_rn(acc, e[j]);
            o[j] = (x > 0) ? __fadd_rn(carry, acc) : acc;
        }
    }
}

// ---------------------------------------------------------------------------
// Kernel C: final composition, chip-wide. One thread per 16-block:
//   s[16r+j] = (r>0 ? ISB1[r-1] + seqprefix : seqprefix), elems recomputed
//   with forced rounding (bit-identical to the stored-elems realization).
// Also emits final_phase for the last block of each batch.
// ---------------------------------------------------------------------------
__global__ void __launch_bounds__(256)
scan_final_kernel(const float* __restrict__ f0,
                  const float* __restrict__ init_phase,
                  float* __restrict__ out, int out_size) {
    const int rg = blockIdx.x * blockDim.x + threadIdx.x;
    if (rg >= BB * 3000) return;
    const int b  = rg / 3000;
    const int rl = rg - b * 3000;

    const float carry = (rl > 0) ? g_isb1[b][rl - 1] : 0.0f;
    const bool  hasc  = (rl > 0);
    const float4* src = reinterpret_cast<const float4*>(
        f0 + (size_t)b * TT + 16 * rl);
    float4* dst = reinterpret_cast<float4*>(g_scan[b] + 16 * rl);

    float acc = 0.0f;
    float last = 0.0f;
#pragma unroll
    for (int v = 0; v < 4; v++) {
        float4 x = src[v];
        float4 o;
        acc = __fadd_rn(acc, elem_of(x.x));
        o.x = hasc ? __fadd_rn(carry, acc) : acc;
        acc = __fadd_rn(acc, elem_of(x.y));
        o.y = hasc ? __fadd_rn(carry, acc) : acc;
        acc = __fadd_rn(acc, elem_of(x.z));
        o.z = hasc ? __fadd_rn(carry, acc) : acc;
        acc = __fadd_rn(acc, elem_of(x.w));
        o.w = hasc ? __fadd_rn(carry, acc) : acc;
        dst[v] = o;
        last = o.w;
    }

    if (rl == 2999 && out_size >= BB * TT + BB) {
        float ph = last + init_phase[b];
        out[BB * TT + b] = fmodf(ph, C1_2PI);
    }
}

// ---------------------------------------------------------------------------
// Kernel 2: main oscillator (exact round-11 form). One thread per (b, t).
// ---------------------------------------------------------------------------
__global__ void __launch_bounds__(256)
osc_kernel(const float* __restrict__ f0g,
           const float* __restrict__ amps,
           const float* __restrict__ ffq,
           const float* __restrict__ fbw,
           const float* __restrict__ fam,
           const float* __restrict__ init_phase,
           float* __restrict__ out) {
    const int idx = blockIdx.x * blockDim.x + threadIdx.x;
    if (idx >= BB * TT) return;
    const int b = idx / TT;
    const int t = idx - b * TT;

    const float f0    = f0g[idx];
    const float phase = g_scan[b][t] + init_phase[b];

    // Linear interp of formant params (align_corners=True), fp32 like ref.
    const float K = (float)(99.0 / 47999.0);
    float src = (float)t * K;
    int i0 = (int)floorf(src);
    i0 = min(max(i0, 0), CC - 2);
    const float frac = src - (float)i0;
    const float w0 = 1.0f - frac;

    const int base0 = (b * CC + i0) * NFF;
    const int base1 = base0 + NFF;

    float freq[NFF], bwsq[NFF], num[NFF];
#pragma unroll
    for (int f = 0; f < NFF; f++) {
        float fr = ffq[base0 + f] * w0 + ffq[base1 + f] * frac;
        float bw = fbw[base0 + f] * w0 + fbw[base1 + f] * frac;
        float am = fam[base0 + f] * w0 + fam[base1 + f] * frac;
        freq[f] = fr;
        bwsq[f] = bw * bw;
        num[f]  = (am * bw) * bw;
    }

    const float4* av = reinterpret_cast<const float4*>(amps + (size_t)idx * HH);

    float acc = 0.0f;
    float hfv = 1.0f;
#pragma unroll 1
    for (int j = 0; j < HH / 4; j++) {
        float4 a4 = av[j];
        float aarr[4] = {a4.x, a4.y, a4.z, a4.w};
#pragma unroll
        for (int u = 0; u < 4; u++) {
            const float hfreq = f0 * hfv;
            const float x     = phase * hfv;
            const float osc   = accurate_sin_pos(x);
            float fac = 1.0f;
#pragma unroll
            for (int f = 0; f < NFF; f++) {
                float d   = hfreq - freq[f];
                float den = fmaf(d, d, bwsq[f]);
                fac *= 1.0f + __fdividef(num[f], den);
            }
            float a = (hfreq < 12000.0f) ? aarr[u] : 0.0f;
            acc = fmaf(osc * fac, a, acc);
            hfv += 1.0f;
        }
    }

    out[idx] = (f0 > 0.0f) ? acc : 0.0f;
}

// ---------------------------------------------------------------------------
extern "C" void kernel_launch(void* const* d_in, const int* in_sizes, int n_in,
                              void* d_out, int out_size) {
    const float* f0   = (const float*)d_in[0];
    const float* amps = (const float*)d_in[1];
    const float* ffq  = (const float*)d_in[2];
    const float* fbw  = (const float*)d_in[3];
    const float* fam  = (const float*)d_in[4];
    const float* ip   = (const float*)d_in[5];
    float* out = (float*)d_out;

    const int nblk16 = BB * 3000;                       // 24000
    scan_b1_kernel<<<(nblk16 + 255) / 256, 256>>>(f0);
    scan_upper_kernel<<<BB, 256>>>();
    scan_final_kernel<<<(nblk16 + 255) / 256, 256>>>(f0, ip, out, out_size);

    const int total = BB * TT;
    osc_kernel<<<(total + 255) / 256, 256>>>(f0, amps, ffq, fbw, fam, ip, out);
}

// round 16
// speedup vs baseline: 2.3610x; 1.3945x over previous
#include <cuda_runtime.h>
#include <cstdint>

// Problem constants
#define BB  8
#define TT  48000
#define HH  60
#define CC  100
#define NFF 5

// Global intermediates
__device__ float g_b1[BB][3000];     // level-1 block sums
__device__ float g_isb1[BB][3000];   // inclusive scan of B1 (composed)
__device__ float g_scan[BB][TT];     // final phase cumsum

#define C1_2PI 6.2831854820251465f
#define RINV24 (1.0f / 24000.0f)

// ---------------------------------------------------------------------------
// f32x2 packed helpers (per-lane IEEE f32 RN; PTX ISA 8.6, sm_100+)
// ---------------------------------------------------------------------------
typedef unsigned long long ull;

__device__ __forceinline__ ull pk2(float lo, float hi) {
    ull r; asm("mov.b64 %0, {%1, %2};" : "=l"(r) : "f"(lo), "f"(hi)); return r;
}
__device__ __forceinline__ void upk2(ull v, float& lo, float& hi) {
    asm("mov.b64 {%0, %1}, %2;" : "=f"(lo), "=f"(hi) : "l"(v));
}
__device__ __forceinline__ ull add2(ull a, ull b) {
    ull r; asm("add.rn.f32x2 %0, %1, %2;" : "=l"(r) : "l"(a), "l"(b)); return r;
}
__device__ __forceinline__ ull mul2(ull a, ull b) {
    ull r; asm("mul.rn.f32x2 %0, %1, %2;" : "=l"(r) : "l"(a), "l"(b)); return r;
}
__device__ __forceinline__ ull fma2(ull a, ull b, ull c) {
    ull r; asm("fma.rn.f32x2 %0, %1, %2, %3;" : "=l"(r) : "l"(a), "l"(b), "l"(c));
    return r;
}

// ---------------------------------------------------------------------------
// Accurate sincos for x >= 0, x < ~3.2e5. ~2e-7 abs error, branch-free.
// ---------------------------------------------------------------------------
__device__ __forceinline__ void accurate_sincos_pos(float x, float& s, float& c) {
    float t  = x * 0.636619772367581343f;           // 2/pi
    int   q  = __float2int_rn(t);
    float qf = __int2float_rn(q);
    float r  = fmaf(qf, -1.57079637050628662109375f, x);  // -fl(pi/2)
    r        = fmaf(qf,  4.37113900018370e-8f, r);        // fl(pi/2)-pi/2 tail
    float z  = r * r;
    float ss = fmaf(-1.9515295891e-4f, z, 8.3321608736e-3f);
    ss       = fmaf(ss, z, -1.6666654611e-1f);
    float ps = fmaf(r, z * ss, r);
    float cc = fmaf(2.443315711809948e-5f, z, -1.388731625493765e-3f);
    cc       = fmaf(cc, z, 4.166664568298827e-2f);
    float pc = fmaf(cc, z * z, fmaf(-0.5f, z, 1.0f));
    float sres = (q & 1) ? pc : ps;
    s = (q & 2) ? -sres : sres;
    float cres = (q & 1) ? ps : pc;
    c = ((q + 1) & 2) ? -cres : cres;
}

// elems = fl32( fl32(C1 * f0) * fl32(1/24000) ) — intrinsics forbid FMA
// contraction, reproducing the stored-elems rounding of rounds 11/12.
__device__ __forceinline__ float elem_of(float f0v) {
    return __fmul_rn(__fmul_rn(C1_2PI, f0v), RINV24);
}

// ---------------------------------------------------------------------------
// Kernel A: B1[b][r] = sequential sum of elems[16r..16r+15], chip-wide.
// ---------------------------------------------------------------------------
__global__ void __launch_bounds__(256)
scan_b1_kernel(const float* __restrict__ f0) {
    const int rg = blockIdx.x * blockDim.x + threadIdx.x;
    if (rg >= BB * 3000) return;
    const int b  = rg / 3000;
    const int rl = rg - b * 3000;

    const float4* src = reinterpret_cast<const float4*>(
        f0 + (size_t)b * TT + 16 * rl);
    float acc = 0.0f;
#pragma unroll
    for (int v = 0; v < 4; v++) {
        float4 x = src[v];
        acc = __fadd_rn(acc, elem_of(x.x));
        acc = __fadd_rn(acc, elem_of(x.y));
        acc = __fadd_rn(acc, elem_of(x.z));
        acc = __fadd_rn(acc, elem_of(x.w));
    }
    g_b1[b][rl] = acc;
}

// ---------------------------------------------------------------------------
// Kernel B: upper levels per batch: B2(188) -> B3(12) -> S3 -> ISB2 -> ISB1.
// ---------------------------------------------------------------------------
__global__ void __launch_bounds__(256)
scan_upper_kernel() {
    __shared__ float sb1[3000];
    __shared__ float sb2[188];
    __shared__ float sb3[12];

    const int b   = blockIdx.x;
    const int tid = threadIdx.x;
    const int bd  = blockDim.x;

    for (int i = tid; i < 3000; i += bd) sb1[i] = g_b1[b][i];
    __syncthreads();

    for (int q = tid; q < 188; q += bd) {
        float acc = 0.0f;
        const int nj = min(16, 3000 - 16 * q);
        const float* e = sb1 + 16 * q;
        for (int j = 0; j < nj; j++) acc = __fadd_rn(acc, e[j]);
        sb2[q] = acc;
    }
    __syncthreads();

    if (tid < 12) {
        float acc = 0.0f;
        const int nj = min(16, 188 - 16 * tid);
        const float* e = sb2 + 16 * tid;
        for (int j = 0; j < nj; j++) acc = __fadd_rn(acc, e[j]);
        sb3[tid] = acc;
    }
    __syncthreads();

    if (tid == 0) {
        float acc = 0.0f;
        for (int k = 0; k < 12; k++) {
            acc = __fadd_rn(acc, sb3[k]);
            sb3[k] = acc;
        }
    }
    __syncthreads();

    if (tid < 12) {
        const float carry = (tid > 0) ? sb3[tid - 1] : 0.0f;
        const int nj = min(16, 188 - 16 * tid);
        float acc = 0.0f;
        float* e = sb2 + 16 * tid;
        for (int j = 0; j < nj; j++) {
            acc = __fadd_rn(acc, e[j]);
            e[j] = (tid > 0) ? __fadd_rn(carry, acc) : acc;
        }
    }
    __syncthreads();

    for (int x = tid; x < 188; x += bd) {
        const float carry = (x > 0) ? sb2[x - 1] : 0.0f;
        const int nj = min(16, 3000 - 16 * x);
        float acc = 0.0f;
        const float* e = sb1 + 16 * x;
        float* o = g_isb1[b] + 16 * x;
        for (int j = 0; j < nj; j++) {
            acc = __fadd_rn(acc, e[j]);
            o[j] = (x > 0) ? __fadd_rn(carry, acc) : acc;
        }
    }
}

// ---------------------------------------------------------------------------
// Kernel C: final composition, chip-wide.
// ---------------------------------------------------------------------------
__global__ void __launch_bounds__(256)
scan_final_kernel(const float* __restrict__ f0,
                  const float* __restrict__ init_phase,
                  float* __restrict__ out, int out_size) {
    const int rg = blockIdx.x * blockDim.x + threadIdx.x;
    if (rg >= BB * 3000) return;
    const int b  = rg / 3000;
    const int rl = rg - b * 3000;

    const float carry = (rl > 0) ? g_isb1[b][rl - 1] : 0.0f;
    const bool  hasc  = (rl > 0);
    const float4* src = reinterpret_cast<const float4*>(
        f0 + (size_t)b * TT + 16 * rl);
    float4* dst = reinterpret_cast<float4*>(g_scan[b] + 16 * rl);

    float acc = 0.0f;
    float last = 0.0f;
#pragma unroll
    for (int v = 0; v < 4; v++) {
        float4 x = src[v];
        float4 o;
        acc = __fadd_rn(acc, elem_of(x.x));
        o.x = hasc ? __fadd_rn(carry, acc) : acc;
        acc = __fadd_rn(acc, elem_of(x.y));
        o.y = hasc ? __fadd_rn(carry, acc) : acc;
        acc = __fadd_rn(acc, elem_of(x.z));
        o.z = hasc ? __fadd_rn(carry, acc) : acc;
        acc = __fadd_rn(acc, elem_of(x.w));
        o.w = hasc ? __fadd_rn(carry, acc) : acc;
        dst[v] = o;
        last = o.w;
    }

    if (rl == 2999 && out_size >= BB * TT + BB) {
        float ph = last + init_phase[b];
        out[BB * TT + b] = fmodf(ph, C1_2PI);
    }
}

// ---------------------------------------------------------------------------
// Kernel 2: oscillator, f32x2-packed (2 harmonics per instruction).
//   osc = sin(fl(phase*h)) via rotation recurrence + exact-residual (Dekker)
//         2nd-order correction.
//   factor = Π(den+num)/Π(den), dens exactly prescaled by 2^-10 (no overflow).
//   nyq: fl(f0s*h) < 375  ⟺  fl(f0*h) < 12000 (exact power-of-2 scaling).
// ---------------------------------------------------------------------------
__global__ void __launch_bounds__(256)
osc_kernel(const float* __restrict__ f0g,
           const float* __restrict__ amps,
           const float* __restrict__ ffq,
           const float* __restrict__ fbw,
           const float* __restrict__ fam,
           const float* __restrict__ init_phase,
           float* __restrict__ out) {
    const int idx = blockIdx.x * blockDim.x + threadIdx.x;
    if (idx >= BB * TT) return;
    const int b = idx / TT;
    const int t = idx - b * TT;

    const float f0    = f0g[idx];
    const float phase = g_scan[b][t] + init_phase[b];

    // Linear interp of formant params (align_corners=True), fp32 like ref.
    const float K = (float)(99.0 / 47999.0);
    float src = (float)t * K;
    int i0 = (int)floorf(src);
    i0 = min(max(i0, 0), CC - 2);
    const float frac = src - (float)i0;
    const float w0 = 1.0f - frac;

    const int base0 = (b * CC + i0) * NFF;
    const int base1 = base0 + NFF;

    const float S5  = 0.03125f;        // 2^-5  (exact scaling)
    const float S10 = 9.765625e-4f;    // 2^-10 (exact scaling)

    ull nfreqs2[NFF], bw2s2[NFF], bns2[NFF];
#pragma unroll
    for (int f = 0; f < NFF; f++) {
        float fr = ffq[base0 + f] * w0 + ffq[base1 + f] * frac;
        float bw = fbw[base0 + f] * w0 + fbw[base1 + f] * frac;
        float am = fam[base0 + f] * w0 + fam[base1 + f] * frac;
        float bw2 = __fmul_rn(bw, bw);
        float num = __fmul_rn(__fmul_rn(am, bw), bw);
        float nfs = -__fmul_rn(fr, S5);
        float b2s = __fmul_rn(bw2, S10);
        float bns = __fmul_rn(__fadd_rn(bw2, num), S10);
        nfreqs2[f] = pk2(nfs, nfs);
        bw2s2[f]   = pk2(b2s, b2s);
        bns2[f]    = pk2(bns, bns);
    }

    // Rotation recurrence init: pair (h, h+1) starting at (1, 2), step +2.
    float s1, c1, s2v, c2v;
    accurate_sincos_pos(phase, s1, c1);
    accurate_sincos_pos(phase + phase, s2v, c2v);

    ull s2   = pk2(s1, s2v);
    ull c2   = pk2(c1, c2v);
    ull rc2  = pk2(c2v, c2v);            // cos(2*phase)
    ull rs2  = pk2(s2v, s2v);            // sin(2*phase)
    ull nrs2 = pk2(-s2v, -s2v);
    ull ph2  = pk2(phase, phase);
    ull nph2 = pk2(-phase, -phase);
    ull nhf2 = pk2(-0.5f, -0.5f);
    ull two2 = pk2(2.0f, 2.0f);
    ull hf2  = pk2(1.0f, 2.0f);
    const float f0s = __fmul_rn(f0, S5);
    ull f0s2 = pk2(f0s, f0s);
    ull acc2 = pk2(0.0f, 0.0f);

    const float4* av = reinterpret_cast<const float4*>(amps + (size_t)idx * HH);

    auto do_pair = [&](float a0, float a1) {
        // scaled harmonic freq + nyquist mask
        ull hfs2 = mul2(f0s2, hf2);
        float hl, hh;
        upk2(hfs2, hl, hh);
        float am0 = (hl < 375.0f) ? a0 : 0.0f;
        float am1 = (hh < 375.0f) ? a1 : 0.0f;

        // formant resonance products
        ull P1, P2;
        {
            ull d2 = add2(hfs2, nfreqs2[0]);
            P2 = fma2(d2, d2, bw2s2[0]);
            P1 = fma2(d2, d2, bns2[0]);
        }
#pragma unroll
        for (int f = 1; f < NFF; f++) {
            ull d2  = add2(hfs2, nfreqs2[f]);
            ull den = fma2(d2, d2, bw2s2[f]);
            ull dn  = fma2(d2, d2, bns2[f]);
            P2 = mul2(P2, den);
            P1 = mul2(P1, dn);
        }
        float p1l, p1h, p2l, p2h;
        upk2(P1, p1l, p1h);
        upk2(P2, p2l, p2h);
        float facl = __fdividef(p1l, p2l);
        float fach = __fdividef(p1h, p2h);

        // osc = sin(fl(phase*h)) = sin(h*phase + dn), dn = fl - exact
        ull prod2 = mul2(ph2, hf2);
        ull dn2   = fma2(nph2, hf2, prod2);       // exact residual
        ull t2    = mul2(dn2, nhf2);
        ull w2    = fma2(t2, s2, c2);
        ull osc2  = fma2(dn2, w2, s2);

        // accumulate
        ull of2 = mul2(osc2, pk2(facl, fach));
        acc2 = fma2(of2, pk2(am0, am1), acc2);

        // rotate pair by +2 harmonics
        ull tt  = mul2(c2, rs2);
        ull ns2 = fma2(s2, rc2, tt);
        ull uu  = mul2(s2, nrs2);
        c2 = fma2(c2, rc2, uu);
        s2 = ns2;
        hf2 = add2(hf2, two2);
    };

#pragma unroll 3
    for (int j = 0; j < HH / 4; j++) {
        float4 a4 = av[j];
        do_pair(a4.x, a4.y);
        do_pair(a4.z, a4.w);
    }

    float al, ah;
    upk2(acc2, al, ah);
    float res = __fadd_rn(al, ah);
    out[idx] = (f0 > 0.0f) ? res : 0.0f;
}

// ---------------------------------------------------------------------------
extern "C" void kernel_launch(void* const* d_in, const int* in_sizes, int n_in,
                              void* d_out, int out_size) {
    const float* f0   = (const float*)d_in[0];
    const float* amps = (const float*)d_in[1];
    const float* ffq  = (const float*)d_in[2];
    const float* fbw  = (const float*)d_in[3];
    const float* fam  = (const float*)d_in[4];
    const float* ip   = (const float*)d_in[5];
    float* out = (float*)d_out;

    const int nblk16 = BB * 3000;                       // 24000
    scan_b1_kernel<<<(nblk16 + 255) / 256, 256>>>(f0);
    scan_upper_kernel<<<BB, 256>>>();
    scan_final_kernel<<<(nblk16 + 255) / 256, 256>>>(f0, ip, out, out_size);

    const int total = BB * TT;
    osc_kernel<<<(total + 255) / 256, 256>>>(f0, amps, ffq, fbw, fam, ip, out);
}